// round 4
// baseline (speedup 1.0000x reference)
#include <cuda_runtime.h>
#include <cuda_bf16.h>
#include <cstdint>

#define MAXN 50016           // >= N=50000
#define MAXE 1605632         // >= E=1600000
#define BT   64              // batch size

// -------- scratch (__device__ globals; no allocation allowed) --------
__device__ float2 g_xT   [MAXN * (BT / 2)];  // x transposed [N][64], float2 view (12.8 MB)
__device__ int2   g_csr_r[MAXE];             // reaction CSR (by i): {j, bits(wr)}  (12.8 MB)
__device__ int2   g_csr_d[MAXE];             // diffusion CSR (by j): {i, bits(wd)} (12.8 MB)
__device__ int    g_cnt_i[MAXN];
__device__ int    g_cnt_j[MAXN];
__device__ int    g_off_i[MAXN + 1];
__device__ int    g_off_j[MAXN + 1];
__device__ int    g_cur_i[MAXN];
__device__ int    g_cur_j[MAXN];
__device__ float  g_cr  [MAXN];              // col_r[v] = sum wr over edges with j==v
__device__ float  g_cd  [MAXN];              // col_d[v] = sum wd over edges with i==v

// ---------------------------------------------------------------------------
// Kernel 1: transpose input [B,N] -> xT [N,B]
// ---------------------------------------------------------------------------
__global__ void k_transpose_in(const float* __restrict__ in,
                               float* __restrict__ xT, int n) {
    __shared__ float tile[32][BT + 1];
    const int v0 = blockIdx.x * 32;
    const int t  = threadIdx.x;   // 256
    #pragma unroll
    for (int k = t; k < 32 * BT; k += 256) {
        int b = k >> 5, vl = k & 31, v = v0 + vl;
        tile[vl][b] = (v < n) ? in[(size_t)b * n + v] : 0.0f;
    }
    __syncthreads();
    #pragma unroll
    for (int k = t; k < 32 * BT; k += 256) {
        int vl = k >> 6, b = k & 63, v = v0 + vl;
        if (v < n) xT[(size_t)v * BT + b] = tile[vl][b];
    }
}

// ---------------------------------------------------------------------------
// Kernel 2: histogram degrees + column sums (spread-address REDs, cheap)
// ---------------------------------------------------------------------------
__global__ void k_hist(const int* __restrict__ ei, const int* __restrict__ ej,
                       const float* __restrict__ wr, const float* __restrict__ wd,
                       int* cnt_i, int* cnt_j, float* col_r, float* col_d, int e) {
    int k = blockIdx.x * blockDim.x + threadIdx.x;
    if (k >= e) return;
    int i = __ldg(ei + k), j = __ldg(ej + k);
    atomicAdd(cnt_i + i, 1);
    atomicAdd(cnt_j + j, 1);
    atomicAdd(col_r + j, __ldg(wr + k));
    atomicAdd(col_d + i, __ldg(wd + k));
}

// ---------------------------------------------------------------------------
// Kernel 3: exclusive scan of degree counts (one 1024-thread block per array)
// ---------------------------------------------------------------------------
__global__ void k_scan(const int* __restrict__ cnt_i, const int* __restrict__ cnt_j,
                       int* off_i, int* off_j, int* cur_i, int* cur_j, int n) {
    __shared__ int sm[1024];
    const int t = threadIdx.x;
    const int* cnt = blockIdx.x ? cnt_j : cnt_i;
    int* off = blockIdx.x ? off_j : off_i;
    int* cur = blockIdx.x ? cur_j : cur_i;
    const int C  = (n + 1023) >> 10;
    const int lo = t * C;
    const int hi = min(lo + C, n);
    int s = 0;
    for (int k = lo; k < hi; k++) s += cnt[k];
    sm[t] = s;
    __syncthreads();
    #pragma unroll
    for (int d = 1; d < 1024; d <<= 1) {
        int v = (t >= d) ? sm[t - d] : 0;
        __syncthreads();
        sm[t] += v;
        __syncthreads();
    }
    int run = (t > 0) ? sm[t - 1] : 0;
    for (int k = lo; k < hi; k++) { off[k] = run; cur[k] = run; run += cnt[k]; }
    if (hi == n) off[n] = run;   // all threads past the end write the same total
}

// ---------------------------------------------------------------------------
// Kernel 4: scatter edges into the two CSRs (counting sort)
// ---------------------------------------------------------------------------
__global__ void k_scatter(const int* __restrict__ ei, const int* __restrict__ ej,
                          const float* __restrict__ wr, const float* __restrict__ wd,
                          int* cur_i, int* cur_j,
                          int2* __restrict__ csr_r, int2* __restrict__ csr_d, int e) {
    int k = blockIdx.x * blockDim.x + threadIdx.x;
    if (k >= e) return;
    int i = __ldg(ei + k), j = __ldg(ej + k);
    int p = atomicAdd(cur_i + i, 1);
    csr_r[p] = make_int2(j, __float_as_int(__ldg(wr + k)));
    int q = atomicAdd(cur_j + j, 1);
    csr_d[q] = make_int2(i, __float_as_int(__ldg(wd + k)));
}

// ---------------------------------------------------------------------------
// Kernel 5: main pass. One warp per node; both directions; accumulators in
// registers (float2/lane = 64 floats/warp); fused combine; staged coalesced out.
// Gather loop is pipelined 4-deep for MLP.
// ---------------------------------------------------------------------------
__device__ __forceinline__ void seg_accum(const int2* __restrict__ csr,
                                          int s0, int s1, int lane,
                                          const float2* __restrict__ xT2,
                                          float2& acc) {
    for (int base = s0; base < s1; base += 32) {
        const int cnt = min(32, s1 - base);
        int2 e = (lane < cnt) ? __ldg(&csr[base + lane]) : make_int2(0, 0);
        int s = 0;
        for (; s + 4 <= cnt; s += 4) {
            int   n0 = __shfl_sync(0xffffffffu, e.x, s + 0);
            int   n1 = __shfl_sync(0xffffffffu, e.x, s + 1);
            int   n2 = __shfl_sync(0xffffffffu, e.x, s + 2);
            int   n3 = __shfl_sync(0xffffffffu, e.x, s + 3);
            // issue all gathers before any FMA -> 4 loads in flight per warp
            float2 x0 = __ldg(&xT2[n0 * 32 + lane]);
            float2 x1 = __ldg(&xT2[n1 * 32 + lane]);
            float2 x2 = __ldg(&xT2[n2 * 32 + lane]);
            float2 x3 = __ldg(&xT2[n3 * 32 + lane]);
            float w0 = __int_as_float(__shfl_sync(0xffffffffu, e.y, s + 0));
            float w1 = __int_as_float(__shfl_sync(0xffffffffu, e.y, s + 1));
            float w2 = __int_as_float(__shfl_sync(0xffffffffu, e.y, s + 2));
            float w3 = __int_as_float(__shfl_sync(0xffffffffu, e.y, s + 3));
            acc.x += w0 * x0.x; acc.y += w0 * x0.y;
            acc.x += w1 * x1.x; acc.y += w1 * x1.y;
            acc.x += w2 * x2.x; acc.y += w2 * x2.y;
            acc.x += w3 * x3.x; acc.y += w3 * x3.y;
        }
        for (; s < cnt; s++) {
            int   nn = __shfl_sync(0xffffffffu, e.x, s);
            float ww = __int_as_float(__shfl_sync(0xffffffffu, e.y, s));
            float2 xo = __ldg(&xT2[nn * 32 + lane]);
            acc.x += ww * xo.x; acc.y += ww * xo.y;
        }
    }
}

__global__ void k_node(const int2*  __restrict__ csr_r,
                       const int2*  __restrict__ csr_d,
                       const int*   __restrict__ off_i,
                       const int*   __restrict__ off_j,
                       const float2* __restrict__ xT2,
                       const float* __restrict__ cr,
                       const float* __restrict__ cd,
                       const float* __restrict__ br,
                       const float* __restrict__ bd,
                       float* __restrict__ out, int n) {
    __shared__ float tile[BT][9];          // [batch][node-in-block], padded
    const int w    = threadIdx.x >> 5;     // 8 warps -> 8 nodes
    const int lane = threadIdx.x & 31;
    const int v    = blockIdx.x * 8 + w;

    if (v < n) {
        float2 acc_r = make_float2(0.f, 0.f);
        float2 acc_d = make_float2(0.f, 0.f);
        float2 xv = __ldg(&xT2[v * 32 + lane]);

        seg_accum(csr_r, __ldg(off_i + v), __ldg(off_i + v + 1), lane, xT2, acc_r);
        seg_accum(csr_d, __ldg(off_j + v), __ldg(off_j + v + 1), lane, xT2, acc_d);

        const float crv = __ldg(cr + v), cdv = __ldg(cd + v);
        const float brv = __ldg(br + v), bdv = __ldg(bd + v);
        float ox = tanhf(crv * xv.x - acc_r.x + brv) + (cdv * xv.x - acc_d.x + bdv) + xv.x;
        float oy = tanhf(crv * xv.y - acc_r.y + brv) + (cdv * xv.y - acc_d.y + bdv) + xv.y;
        tile[2 * lane    ][w] = ox;
        tile[2 * lane + 1][w] = oy;
    }
    __syncthreads();

    const int v0 = blockIdx.x * 8;
    #pragma unroll
    for (int k = threadIdx.x; k < BT * 8; k += 256) {
        int b = k >> 3, wl = k & 7;
        if (v0 + wl < n) out[(size_t)b * n + v0 + wl] = tile[b][wl];
    }
}

// ---------------------------------------------------------------------------
// Launch. Inputs: t, input, edge_i, edge_j, weight_react, weight_diff,
//                 bias_reaction, bias_diffusion. Output fp32 [B, N].
// ---------------------------------------------------------------------------
extern "C" void kernel_launch(void* const* d_in, const int* in_sizes, int n_in,
                              void* d_out, int out_size) {
    const float* input = (const float*)d_in[1];
    const int*   ei    = (const int*)  d_in[2];
    const int*   ej    = (const int*)  d_in[3];
    const float* wr    = (const float*)d_in[4];
    const float* wd    = (const float*)d_in[5];
    const float* br    = (const float*)d_in[6];
    const float* bd    = (const float*)d_in[7];
    float*       out   = (float*)d_out;

    const int n = in_sizes[6];
    const int e = in_sizes[2];

    void *pxT, *pcsr_r, *pcsr_d, *pcnt_i, *pcnt_j, *poff_i, *poff_j,
         *pcur_i, *pcur_j, *pcr, *pcd;
    cudaGetSymbolAddress(&pxT,   g_xT);
    cudaGetSymbolAddress(&pcsr_r, g_csr_r);
    cudaGetSymbolAddress(&pcsr_d, g_csr_d);
    cudaGetSymbolAddress(&pcnt_i, g_cnt_i);
    cudaGetSymbolAddress(&pcnt_j, g_cnt_j);
    cudaGetSymbolAddress(&poff_i, g_off_i);
    cudaGetSymbolAddress(&poff_j, g_off_j);
    cudaGetSymbolAddress(&pcur_i, g_cur_i);
    cudaGetSymbolAddress(&pcur_j, g_cur_j);
    cudaGetSymbolAddress(&pcr,    g_cr);
    cudaGetSymbolAddress(&pcd,    g_cd);

    cudaMemsetAsync(pcnt_i, 0, (size_t)n * sizeof(int));
    cudaMemsetAsync(pcnt_j, 0, (size_t)n * sizeof(int));
    cudaMemsetAsync(pcr,    0, (size_t)n * sizeof(float));
    cudaMemsetAsync(pcd,    0, (size_t)n * sizeof(float));

    const int nvblocks = (n + 31) / 32;
    k_transpose_in<<<nvblocks, 256>>>(input, (float*)pxT, n);

    const int eblocks = (e + 255) / 256;
    k_hist<<<eblocks, 256>>>(ei, ej, wr, wd,
                             (int*)pcnt_i, (int*)pcnt_j,
                             (float*)pcr, (float*)pcd, e);

    k_scan<<<2, 1024>>>((const int*)pcnt_i, (const int*)pcnt_j,
                        (int*)poff_i, (int*)poff_j,
                        (int*)pcur_i, (int*)pcur_j, n);

    k_scatter<<<eblocks, 256>>>(ei, ej, wr, wd,
                                (int*)pcur_i, (int*)pcur_j,
                                (int2*)pcsr_r, (int2*)pcsr_d, e);

    const int nblocks = (n + 7) / 8;
    k_node<<<nblocks, 256>>>((const int2*)pcsr_r, (const int2*)pcsr_d,
                             (const int*)poff_i, (const int*)poff_j,
                             (const float2*)pxT,
                             (const float*)pcr, (const float*)pcd,
                             br, bd, out, n);
}

// round 7
// speedup vs baseline: 1.3349x; 1.3349x over previous
#include <cuda_runtime.h>
#include <cuda_fp16.h>
#include <cstdint>

#define MAXN 50016          // >= N=50000
#define BT   64             // batch size

// -------- scratch (__device__ globals; no allocation allowed) --------
__device__ float  g_xT [MAXN * BT];          // x transposed [N][64] fp32 (12.8 MB)
__device__ __half g_xTh[MAXN * BT];          // x transposed [N][64] fp16 ( 6.4 MB)
__device__ float4 g_mr [MAXN * (BT / 4)];    // reaction messages  [N][64] (12.8 MB)
__device__ float4 g_md [MAXN * (BT / 4)];    // diffusion messages [N][64] (12.8 MB)
__device__ float  g_cr [MAXN];               // reaction col sums
__device__ float  g_cd [MAXN];               // diffusion col sums

// 16-byte vector reduction to global (sm_90+): RED.128 in SASS, no return.
__device__ __forceinline__ void red_add_v4(float* p, float a, float b, float c, float d) {
    asm volatile("red.global.add.v4.f32 [%0], {%1, %2, %3, %4};"
                 :: "l"(p), "f"(a), "f"(b), "f"(c), "f"(d)
                 : "memory");
}

// ---------------------------------------------------------------------------
// Kernel 1: transpose input [B,N] -> xT [N,B] (fp32) + xTh [N,B] (fp16)
// ---------------------------------------------------------------------------
__global__ void k_transpose_in(const float* __restrict__ in,
                               float* __restrict__ xT,
                               __half* __restrict__ xTh, int n) {
    __shared__ float tile[32][BT + 1];
    const int v0 = blockIdx.x * 32;
    const int t  = threadIdx.x;            // 256 threads
    #pragma unroll
    for (int k = t; k < 32 * BT; k += 256) {
        int b = k >> 5, vl = k & 31, v = v0 + vl;
        tile[vl][b] = (v < n) ? in[(size_t)b * n + v] : 0.0f;
    }
    __syncthreads();
    #pragma unroll
    for (int k = t; k < 32 * BT; k += 256) {
        int vl = k >> 6, b = k & 63, v = v0 + vl;
        if (v < n) {
            float x = tile[vl][b];
            size_t idx = (size_t)v * BT + b;
            xT [idx] = x;
            xTh[idx] = __float2half(x);
        }
    }
}

// ---------------------------------------------------------------------------
// Kernel 2: COO edge pass, fp16 gathers + fp32 vector REDs.
// One warp per 32-edge chunk. Lanes 0-15: reaction, 16-31: diffusion.
// Each half-warp covers a 64-float row: lane q handles 4 consecutive values.
//   reaction : msg_r[i] += wr * x[j] ; col_r[j] += wr
//   diffusion: msg_d[j] += wd * x[i] ; col_d[i] += wd
// ---------------------------------------------------------------------------
__global__ void __launch_bounds__(256)
k_edge_pass(const int*    __restrict__ ei,
            const int*    __restrict__ ej,
            const float*  __restrict__ wr,
            const float*  __restrict__ wd,
            const __half* __restrict__ xTh,
            float*  __restrict__ mr,
            float*  __restrict__ md,
            float*  __restrict__ cr,
            float*  __restrict__ cd,
            int e) {
    const int gw   = (blockIdx.x * blockDim.x + threadIdx.x) >> 5;
    const int lane = threadIdx.x & 31;
    const int base = gw * 32;
    if (base >= e) return;
    const int cnt = min(32, e - base);

    int   i_l = 0, j_l = 0;
    float wr_l = 0.f, wd_l = 0.f;
    if (lane < cnt) {
        i_l  = __ldg(ei + base + lane);
        j_l  = __ldg(ej + base + lane);
        wr_l = __ldg(wr + base + lane);
        wd_l = __ldg(wd + base + lane);
        atomicAdd(cr + j_l, wr_l);     // spread-address scalar REDs, cheap
        atomicAdd(cd + i_l, wd_l);
    }

    const int half = lane >> 4;        // 0 = reaction, 1 = diffusion
    const int q    = lane & 15;        // quad slot within the 64-float row
    float* const tgt = half ? md : mr;

    int s = 0;
    for (; s + 4 <= cnt; s += 4) {
        int src[4], dst[4];
        float w[4];
        #pragma unroll
        for (int u = 0; u < 4; u++) {
            int   iv = __shfl_sync(0xffffffffu, i_l, s + u);
            int   jv = __shfl_sync(0xffffffffu, j_l, s + u);
            float wrv = __shfl_sync(0xffffffffu, wr_l, s + u);
            float wdv = __shfl_sync(0xffffffffu, wd_l, s + u);
            src[u] = half ? iv : jv;
            dst[u] = half ? jv : iv;
            w[u]   = half ? wdv : wrv;
        }
        // issue all 4 gathers before any math -> MLP=4 per warp
        uint2 h[4];
        #pragma unroll
        for (int u = 0; u < 4; u++)
            h[u] = __ldg((const uint2*)(xTh + src[u] * BT) + q);
        #pragma unroll
        for (int u = 0; u < 4; u++) {
            float2 fa = __half22float2(*(const __half2*)&h[u].x);
            float2 fb = __half22float2(*(const __half2*)&h[u].y);
            red_add_v4(tgt + dst[u] * BT + q * 4,
                       w[u] * fa.x, w[u] * fa.y, w[u] * fb.x, w[u] * fb.y);
        }
    }
    for (; s < cnt; s++) {
        int   iv = __shfl_sync(0xffffffffu, i_l, s);
        int   jv = __shfl_sync(0xffffffffu, j_l, s);
        float wrv = __shfl_sync(0xffffffffu, wr_l, s);
        float wdv = __shfl_sync(0xffffffffu, wd_l, s);
        int   src = half ? iv : jv;
        int   dst = half ? jv : iv;
        float w   = half ? wdv : wrv;
        uint2 h = __ldg((const uint2*)(xTh + src * BT) + q);
        float2 fa = __half22float2(*(const __half2*)&h.x);
        float2 fb = __half22float2(*(const __half2*)&h.y);
        red_add_v4(tgt + dst * BT + q * 4,
                   w * fa.x, w * fa.y, w * fb.x, w * fb.y);
    }
}

// ---------------------------------------------------------------------------
// Kernel 3: combine + transpose out.
//   out[b,v] = tanh(cr[v]*x - mr[v,b] + br[v]) + (cd[v]*x - md[v,b] + bd[v]) + x
// ---------------------------------------------------------------------------
__global__ void k_combine(const float* __restrict__ xT,
                          const float* __restrict__ mr,
                          const float* __restrict__ md,
                          const float* __restrict__ cr,
                          const float* __restrict__ cd,
                          const float* __restrict__ br,
                          const float* __restrict__ bd,
                          float* __restrict__ out, int n) {
    __shared__ float tile[32][BT + 1];
    const int v0 = blockIdx.x * 32;
    const int t  = threadIdx.x;
    #pragma unroll
    for (int k = t; k < 32 * BT; k += 256) {
        int vl = k >> 6, b = k & 63, v = v0 + vl;
        if (v < n) {
            size_t idx = (size_t)v * BT + b;
            float x  = xT[idx];
            float rr = cr[v] * x - mr[idx] + br[v];
            float dd = cd[v] * x - md[idx] + bd[v];
            tile[vl][b] = tanhf(rr) + dd + x;
        }
    }
    __syncthreads();
    #pragma unroll
    for (int k = t; k < 32 * BT; k += 256) {
        int b = k >> 5, vl = k & 31, v = v0 + vl;
        if (v < n) out[(size_t)b * n + v] = tile[vl][b];
    }
}

// ---------------------------------------------------------------------------
// Launch. Inputs: t, input, edge_i, edge_j, weight_react, weight_diff,
//                 bias_reaction, bias_diffusion. Output fp32 [B, N].
// ---------------------------------------------------------------------------
extern "C" void kernel_launch(void* const* d_in, const int* in_sizes, int n_in,
                              void* d_out, int out_size) {
    const float* input = (const float*)d_in[1];
    const int*   ei    = (const int*)  d_in[2];
    const int*   ej    = (const int*)  d_in[3];
    const float* wr    = (const float*)d_in[4];
    const float* wd    = (const float*)d_in[5];
    const float* br    = (const float*)d_in[6];
    const float* bd    = (const float*)d_in[7];
    float*       out   = (float*)d_out;

    const int n = in_sizes[6];   // bias_reaction has N elements
    const int e = in_sizes[2];   // edge count

    void *pxT, *pxTh, *pmr, *pmd, *pcr, *pcd;
    cudaGetSymbolAddress(&pxT,  g_xT);
    cudaGetSymbolAddress(&pxTh, g_xTh);
    cudaGetSymbolAddress(&pmr,  g_mr);
    cudaGetSymbolAddress(&pmd,  g_md);
    cudaGetSymbolAddress(&pcr,  g_cr);
    cudaGetSymbolAddress(&pcd,  g_cd);

    cudaMemsetAsync(pmr, 0, (size_t)n * BT * sizeof(float));
    cudaMemsetAsync(pmd, 0, (size_t)n * BT * sizeof(float));
    cudaMemsetAsync(pcr, 0, (size_t)n * sizeof(float));
    cudaMemsetAsync(pcd, 0, (size_t)n * sizeof(float));

    const int nvblocks = (n + 31) / 32;
    k_transpose_in<<<nvblocks, 256>>>(input, (float*)pxT, (__half*)pxTh, n);

    const int nchunks = (e + 31) / 32;      // one warp per 32-edge chunk
    const int eblocks = (nchunks + 7) / 8;  // 8 warps per block
    k_edge_pass<<<eblocks, 256>>>(ei, ej, wr, wd,
                                  (const __half*)pxTh,
                                  (float*)pmr, (float*)pmd,
                                  (float*)pcr, (float*)pcd, e);

    k_combine<<<nvblocks, 256>>>((const float*)pxT,
                                 (const float*)pmr, (const float*)pmd,
                                 (const float*)pcr, (const float*)pcd,
                                 br, bd, out, n);
}

// round 9
// speedup vs baseline: 1.6245x; 1.2170x over previous
#include <cuda_runtime.h>
#include <cuda_fp16.h>
#include <cstdint>

#define MAXN 50016          // >= N=50000
#define BT   64             // batch size

// -------- scratch (__device__ globals; no allocation allowed) --------
__device__ float  g_xT [MAXN * BT];          // x transposed [N][64] fp32 (12.8 MB)
__device__ __half g_xTh[MAXN * BT];          // x transposed [N][64] fp16 ( 6.4 MB)
__device__ float4 g_mr [MAXN * (BT / 4)];    // reaction messages [N][64] fp32 (12.8 MB)
__device__ __half g_md [MAXN * BT];          // diffusion messages [N][64] fp16 (6.4 MB)
__device__ float  g_cr [MAXN];               // reaction col sums
__device__ float  g_cd [MAXN];               // diffusion col sums

// 16-byte fp32 vector reduction (RED.128 in SASS, no return).
__device__ __forceinline__ void red_add_v4(float* p, float a, float b, float c, float d) {
    asm volatile("red.global.add.v4.f32 [%0], {%1, %2, %3, %4};"
                 :: "l"(p), "f"(a), "f"(b), "f"(c), "f"(d)
                 : "memory");
}

// 8-byte fp16x2 vector reduction (4 halves per lane).
__device__ __forceinline__ void red_add_h4(__half* p, float a, float b, float c, float d) {
    __half2 lo = __floats2half2_rn(a, b);
    __half2 hi = __floats2half2_rn(c, d);
    unsigned lou = *(unsigned*)&lo, hiu = *(unsigned*)&hi;
    asm volatile("red.global.add.noftz.v2.f16x2 [%0], {%1, %2};"
                 :: "l"(p), "r"(lou), "r"(hiu)
                 : "memory");
}

// ---------------------------------------------------------------------------
// Kernel 1: transpose input [B,N] -> xT [N,B] (fp32) + xTh [N,B] (fp16)
// ---------------------------------------------------------------------------
__global__ void k_transpose_in(const float* __restrict__ in,
                               float* __restrict__ xT,
                               __half* __restrict__ xTh, int n) {
    __shared__ float tile[32][BT + 1];
    const int v0 = blockIdx.x * 32;
    const int t  = threadIdx.x;            // 256 threads
    #pragma unroll
    for (int k = t; k < 32 * BT; k += 256) {
        int b = k >> 5, vl = k & 31, v = v0 + vl;
        tile[vl][b] = (v < n) ? in[(size_t)b * n + v] : 0.0f;
    }
    __syncthreads();
    #pragma unroll
    for (int k = t; k < 32 * BT; k += 256) {
        int vl = k >> 6, b = k & 63, v = v0 + vl;
        if (v < n) {
            float x = tile[vl][b];
            size_t idx = (size_t)v * BT + b;
            xT [idx] = x;
            xTh[idx] = __float2half(x);
        }
    }
}

// ---------------------------------------------------------------------------
// Kernel 2: COO edge pass. fp16 gathers; fp32 REDs for reaction, fp16 REDs
// for diffusion (weights are /1000 -> fp16 accumulation error ~1e-5 rel).
// One warp per 32-edge chunk; lanes 0-15 reaction, 16-31 diffusion;
// each half-warp lane owns 4 consecutive batch slots.
//   reaction : msg_r[i] += wr * x[j] ; col_r[j] += wr
//   diffusion: msg_d[j] += wd * x[i] ; col_d[i] += wd
// ---------------------------------------------------------------------------
__global__ void __launch_bounds__(256)
k_edge_pass(const int*    __restrict__ ei,
            const int*    __restrict__ ej,
            const float*  __restrict__ wr,
            const float*  __restrict__ wd,
            const __half* __restrict__ xTh,
            float*  __restrict__ mr,
            __half* __restrict__ md,
            float*  __restrict__ cr,
            float*  __restrict__ cd,
            int e) {
    const int gw   = (blockIdx.x * blockDim.x + threadIdx.x) >> 5;
    const int lane = threadIdx.x & 31;
    const int base = gw * 32;
    if (base >= e) return;
    const int cnt = min(32, e - base);

    int   i_l = 0, j_l = 0;
    float wr_l = 0.f, wd_l = 0.f;
    if (lane < cnt) {
        i_l  = __ldg(ei + base + lane);
        j_l  = __ldg(ej + base + lane);
        wr_l = __ldg(wr + base + lane);
        wd_l = __ldg(wd + base + lane);
        atomicAdd(cr + j_l, wr_l);     // spread-address scalar REDs, cheap
        atomicAdd(cd + i_l, wd_l);
    }

    const int half = lane >> 4;        // 0 = reaction, 1 = diffusion
    const int q    = lane & 15;        // quad slot within the 64-value row

    int s = 0;
    for (; s + 4 <= cnt; s += 4) {
        int src[4], dst[4];
        float w[4];
        #pragma unroll
        for (int u = 0; u < 4; u++) {
            int   iv  = __shfl_sync(0xffffffffu, i_l, s + u);
            int   jv  = __shfl_sync(0xffffffffu, j_l, s + u);
            float wrv = __shfl_sync(0xffffffffu, wr_l, s + u);
            float wdv = __shfl_sync(0xffffffffu, wd_l, s + u);
            src[u] = half ? iv : jv;
            dst[u] = half ? jv : iv;
            w[u]   = half ? wdv : wrv;
        }
        // issue all 4 gathers before any math -> MLP=4 per warp
        uint2 h[4];
        #pragma unroll
        for (int u = 0; u < 4; u++)
            h[u] = __ldg((const uint2*)(xTh + src[u] * BT) + q);
        if (half == 0) {
            #pragma unroll
            for (int u = 0; u < 4; u++) {
                float2 fa = __half22float2(*(const __half2*)&h[u].x);
                float2 fb = __half22float2(*(const __half2*)&h[u].y);
                red_add_v4(mr + dst[u] * BT + q * 4,
                           w[u] * fa.x, w[u] * fa.y, w[u] * fb.x, w[u] * fb.y);
            }
        } else {
            #pragma unroll
            for (int u = 0; u < 4; u++) {
                float2 fa = __half22float2(*(const __half2*)&h[u].x);
                float2 fb = __half22float2(*(const __half2*)&h[u].y);
                red_add_h4(md + dst[u] * BT + q * 4,
                           w[u] * fa.x, w[u] * fa.y, w[u] * fb.x, w[u] * fb.y);
            }
        }
    }
    for (; s < cnt; s++) {
        int   iv  = __shfl_sync(0xffffffffu, i_l, s);
        int   jv  = __shfl_sync(0xffffffffu, j_l, s);
        float wrv = __shfl_sync(0xffffffffu, wr_l, s);
        float wdv = __shfl_sync(0xffffffffu, wd_l, s);
        int   src = half ? iv : jv;
        int   dst = half ? jv : iv;
        float w   = half ? wdv : wrv;
        uint2 h = __ldg((const uint2*)(xTh + src * BT) + q);
        float2 fa = __half22float2(*(const __half2*)&h.x);
        float2 fb = __half22float2(*(const __half2*)&h.y);
        if (half == 0)
            red_add_v4(mr + dst * BT + q * 4,
                       w * fa.x, w * fa.y, w * fb.x, w * fb.y);
        else
            red_add_h4(md + dst * BT + q * 4,
                       w * fa.x, w * fa.y, w * fb.x, w * fb.y);
    }
}

// ---------------------------------------------------------------------------
// Kernel 3: combine + transpose out.
//   out[b,v] = tanh(cr[v]*x - mr[v,b] + br[v]) + (cd[v]*x - md[v,b] + bd[v]) + x
// ---------------------------------------------------------------------------
__global__ void k_combine(const float* __restrict__ xT,
                          const float* __restrict__ mr,
                          const __half* __restrict__ md,
                          const float* __restrict__ cr,
                          const float* __restrict__ cd,
                          const float* __restrict__ br,
                          const float* __restrict__ bd,
                          float* __restrict__ out, int n) {
    __shared__ float tile[32][BT + 1];
    const int v0 = blockIdx.x * 32;
    const int t  = threadIdx.x;
    #pragma unroll
    for (int k = t; k < 32 * BT; k += 256) {
        int vl = k >> 6, b = k & 63, v = v0 + vl;
        if (v < n) {
            size_t idx = (size_t)v * BT + b;
            float x  = xT[idx];
            float rr = cr[v] * x - mr[idx] + br[v];
            float dd = cd[v] * x - __half2float(md[idx]) + bd[v];
            tile[vl][b] = tanhf(rr) + dd + x;
        }
    }
    __syncthreads();
    #pragma unroll
    for (int k = t; k < 32 * BT; k += 256) {
        int b = k >> 5, vl = k & 31, v = v0 + vl;
        if (v < n) out[(size_t)b * n + v] = tile[vl][b];
    }
}

// ---------------------------------------------------------------------------
// Launch. Inputs: t, input, edge_i, edge_j, weight_react, weight_diff,
//                 bias_reaction, bias_diffusion. Output fp32 [B, N].
// ---------------------------------------------------------------------------
extern "C" void kernel_launch(void* const* d_in, const int* in_sizes, int n_in,
                              void* d_out, int out_size) {
    const float* input = (const float*)d_in[1];
    const int*   ei    = (const int*)  d_in[2];
    const int*   ej    = (const int*)  d_in[3];
    const float* wr    = (const float*)d_in[4];
    const float* wd    = (const float*)d_in[5];
    const float* br    = (const float*)d_in[6];
    const float* bd    = (const float*)d_in[7];
    float*       out   = (float*)d_out;

    const int n = in_sizes[6];   // bias_reaction has N elements
    const int e = in_sizes[2];   // edge count

    void *pxT, *pxTh, *pmr, *pmd, *pcr, *pcd;
    cudaGetSymbolAddress(&pxT,  g_xT);
    cudaGetSymbolAddress(&pxTh, g_xTh);
    cudaGetSymbolAddress(&pmr,  g_mr);
    cudaGetSymbolAddress(&pmd,  g_md);
    cudaGetSymbolAddress(&pcr,  g_cr);
    cudaGetSymbolAddress(&pcd,  g_cd);

    cudaMemsetAsync(pmr, 0, (size_t)n * BT * sizeof(float));
    cudaMemsetAsync(pmd, 0, (size_t)n * BT * sizeof(__half));
    cudaMemsetAsync(pcr, 0, (size_t)n * sizeof(float));
    cudaMemsetAsync(pcd, 0, (size_t)n * sizeof(float));

    const int nvblocks = (n + 31) / 32;
    k_transpose_in<<<nvblocks, 256>>>(input, (float*)pxT, (__half*)pxTh, n);

    const int nchunks = (e + 31) / 32;      // one warp per 32-edge chunk
    const int eblocks = (nchunks + 7) / 8;  // 8 warps per block
    k_edge_pass<<<eblocks, 256>>>(ei, ej, wr, wd,
                                  (const __half*)pxTh,
                                  (float*)pmr, (__half*)pmd,
                                  (float*)pcr, (float*)pcd, e);

    k_combine<<<nvblocks, 256>>>((const float*)pxT,
                                 (const float*)pmr, (const __half*)pmd,
                                 (const float*)pcr, (const float*)pcd,
                                 br, bd, out, n);
}

// round 12
// speedup vs baseline: 2.1658x; 1.3332x over previous
#include <cuda_runtime.h>
#include <cuda_fp16.h>
#include <cstdint>

#define MAXN 50016          // >= N=50000, and == 32*ceil(50000/32)
#define BT   64             // batch size

// -------- scratch (__device__ globals; no allocation allowed) --------
__device__ __half g_xTh[MAXN * BT];   // x transposed [N][64] fp16 (6.4 MB)
__device__ __half g_mrh[MAXN * BT];   // reaction messages  [N][64] fp16 (6.4 MB)
__device__ __half g_md [MAXN * BT];   // diffusion messages [N][64] fp16 (6.4 MB)
__device__ float  g_cr [MAXN];        // reaction col sums
__device__ float  g_cd [MAXN];        // diffusion col sums

// 8-byte fp16x2 vector reduction (4 halves per lane), subnormal-preserving.
__device__ __forceinline__ void red_add_h4(__half* p, float a, float b, float c, float d) {
    __half2 lo = __floats2half2_rn(a, b);
    __half2 hi = __floats2half2_rn(c, d);
    unsigned lou = *(unsigned*)&lo, hiu = *(unsigned*)&hi;
    asm volatile("red.global.add.noftz.v2.f16x2 [%0], {%1, %2};"
                 :: "l"(p), "r"(lou), "r"(hiu)
                 : "memory");
}

// ---------------------------------------------------------------------------
// Kernel 1: prep. Transpose input [B,N] tile -> xTh [N,B] fp16, zero the
// message accumulators for the same node range, zero cr/cd. No memset nodes.
// ---------------------------------------------------------------------------
__global__ void k_prep(const float* __restrict__ in,
                       __half* __restrict__ xTh,
                       __half* __restrict__ mrh,
                       __half* __restrict__ md,
                       float* __restrict__ cr,
                       float* __restrict__ cd, int n) {
    __shared__ float tile[32][BT + 1];
    const int v0 = blockIdx.x * 32;
    const int t  = threadIdx.x;            // 256 threads

    // Zero accumulators for this 32-node slab: 32*64 halves = 4096 B each.
    {
        uint4 z = make_uint4(0, 0, 0, 0);
        uint4* zr = (uint4*)(mrh + (size_t)v0 * BT);
        uint4* zd = (uint4*)(md  + (size_t)v0 * BT);
        zr[t] = z;                          // 256 threads x 16 B = 4096 B
        zd[t] = z;
    }
    if (t < 32) { cr[v0 + t] = 0.0f; cd[v0 + t] = 0.0f; }

    #pragma unroll
    for (int k = t; k < 32 * BT; k += 256) {
        int b = k >> 5, vl = k & 31, v = v0 + vl;
        tile[vl][b] = (v < n) ? in[(size_t)b * n + v] : 0.0f;
    }
    __syncthreads();
    #pragma unroll
    for (int k = t; k < 32 * BT; k += 256) {
        int vl = k >> 6, b = k & 63, v = v0 + vl;
        if (v < n) xTh[(size_t)v * BT + b] = __float2half(tile[vl][b]);
    }
}

// ---------------------------------------------------------------------------
// Kernel 2: COO edge pass. fp16 gathers, fp16 vector REDs both directions.
// One warp per 32-edge chunk; lanes 0-15 reaction, 16-31 diffusion;
// each half-warp lane owns 4 consecutive batch slots (8 B).
//   reaction : mrh[i] += wr * x[j] ; cr[j] += wr
//   diffusion: md [j] += wd * x[i] ; cd[i] += wd
// ---------------------------------------------------------------------------
__global__ void __launch_bounds__(256)
k_edge_pass(const int*    __restrict__ ei,
            const int*    __restrict__ ej,
            const float*  __restrict__ wr,
            const float*  __restrict__ wd,
            const __half* __restrict__ xTh,
            __half* __restrict__ mrh,
            __half* __restrict__ md,
            float*  __restrict__ cr,
            float*  __restrict__ cd,
            int e) {
    const int gw   = (blockIdx.x * blockDim.x + threadIdx.x) >> 5;
    const int lane = threadIdx.x & 31;
    const int base = gw * 32;
    if (base >= e) return;
    const int cnt = min(32, e - base);

    int   i_l = 0, j_l = 0;
    float wr_l = 0.f, wd_l = 0.f;
    if (lane < cnt) {
        i_l  = __ldg(ei + base + lane);
        j_l  = __ldg(ej + base + lane);
        wr_l = __ldg(wr + base + lane);
        wd_l = __ldg(wd + base + lane);
        atomicAdd(cr + j_l, wr_l);     // spread-address scalar REDs, cheap
        atomicAdd(cd + i_l, wd_l);
    }

    const int half = lane >> 4;        // 0 = reaction, 1 = diffusion
    const int q    = lane & 15;        // quad slot within the 64-value row
    __half* const tgt = half ? md : mrh;

    int s = 0;
    for (; s + 4 <= cnt; s += 4) {
        int src[4], dst[4];
        float w[4];
        #pragma unroll
        for (int u = 0; u < 4; u++) {
            int   iv  = __shfl_sync(0xffffffffu, i_l, s + u);
            int   jv  = __shfl_sync(0xffffffffu, j_l, s + u);
            float wrv = __shfl_sync(0xffffffffu, wr_l, s + u);
            float wdv = __shfl_sync(0xffffffffu, wd_l, s + u);
            src[u] = half ? iv : jv;
            dst[u] = half ? jv : iv;
            w[u]   = half ? wdv : wrv;
        }
        // issue all 4 gathers before any math -> MLP=4 per warp
        uint2 h[4];
        #pragma unroll
        for (int u = 0; u < 4; u++)
            h[u] = __ldg((const uint2*)(xTh + src[u] * BT) + q);
        #pragma unroll
        for (int u = 0; u < 4; u++) {
            float2 fa = __half22float2(*(const __half2*)&h[u].x);
            float2 fb = __half22float2(*(const __half2*)&h[u].y);
            red_add_h4(tgt + dst[u] * BT + q * 4,
                       w[u] * fa.x, w[u] * fa.y, w[u] * fb.x, w[u] * fb.y);
        }
    }
    for (; s < cnt; s++) {
        int   iv  = __shfl_sync(0xffffffffu, i_l, s);
        int   jv  = __shfl_sync(0xffffffffu, j_l, s);
        float wrv = __shfl_sync(0xffffffffu, wr_l, s);
        float wdv = __shfl_sync(0xffffffffu, wd_l, s);
        int   src = half ? iv : jv;
        int   dst = half ? jv : iv;
        float w   = half ? wdv : wrv;
        uint2 h = __ldg((const uint2*)(xTh + src * BT) + q);
        float2 fa = __half22float2(*(const __half2*)&h.x);
        float2 fb = __half22float2(*(const __half2*)&h.y);
        red_add_h4(tgt + dst * BT + q * 4,
                   w * fa.x, w * fa.y, w * fb.x, w * fb.y);
    }
}

// ---------------------------------------------------------------------------
// Kernel 3: combine + transpose out. x re-read from input (L2-warm), staged
// through smem so every global access is coalesced.
//   out[b,v] = tanh(cr[v]*x - mrh[v,b] + br[v]) + (cd[v]*x - md[v,b] + bd[v]) + x
// ---------------------------------------------------------------------------
__global__ void k_combine(const float* __restrict__ in,
                          const __half* __restrict__ mrh,
                          const __half* __restrict__ md,
                          const float* __restrict__ cr,
                          const float* __restrict__ cd,
                          const float* __restrict__ br,
                          const float* __restrict__ bd,
                          float* __restrict__ out, int n) {
    __shared__ float xt[32][BT + 1];
    __shared__ float ot[32][BT + 1];
    const int v0 = blockIdx.x * 32;
    const int t  = threadIdx.x;

    #pragma unroll
    for (int k = t; k < 32 * BT; k += 256) {     // coalesced over v
        int b = k >> 5, vl = k & 31, v = v0 + vl;
        xt[vl][b] = (v < n) ? in[(size_t)b * n + v] : 0.0f;
    }
    __syncthreads();
    #pragma unroll
    for (int k = t; k < 32 * BT; k += 256) {     // coalesced over b (fp16 rows)
        int vl = k >> 6, b = k & 63, v = v0 + vl;
        if (v < n) {
            size_t idx = (size_t)v * BT + b;
            float x  = xt[vl][b];
            float rr = cr[v] * x - __half2float(mrh[idx]) + br[v];
            float dd = cd[v] * x - __half2float(md[idx])  + bd[v];
            ot[vl][b] = tanhf(rr) + dd + x;
        }
    }
    __syncthreads();
    #pragma unroll
    for (int k = t; k < 32 * BT; k += 256) {     // coalesced over v
        int b = k >> 5, vl = k & 31, v = v0 + vl;
        if (v < n) out[(size_t)b * n + v] = ot[vl][b];
    }
}

// ---------------------------------------------------------------------------
// Launch. Inputs: t, input, edge_i, edge_j, weight_react, weight_diff,
//                 bias_reaction, bias_diffusion. Output fp32 [B, N].
// ---------------------------------------------------------------------------
extern "C" void kernel_launch(void* const* d_in, const int* in_sizes, int n_in,
                              void* d_out, int out_size) {
    const float* input = (const float*)d_in[1];
    const int*   ei    = (const int*)  d_in[2];
    const int*   ej    = (const int*)  d_in[3];
    const float* wr    = (const float*)d_in[4];
    const float* wd    = (const float*)d_in[5];
    const float* br    = (const float*)d_in[6];
    const float* bd    = (const float*)d_in[7];
    float*       out   = (float*)d_out;

    const int n = in_sizes[6];   // bias_reaction has N elements
    const int e = in_sizes[2];   // edge count

    void *pxTh, *pmrh, *pmd, *pcr, *pcd;
    cudaGetSymbolAddress(&pxTh, g_xTh);
    cudaGetSymbolAddress(&pmrh, g_mrh);
    cudaGetSymbolAddress(&pmd,  g_md);
    cudaGetSymbolAddress(&pcr,  g_cr);
    cudaGetSymbolAddress(&pcd,  g_cd);

    const int nvblocks = (n + 31) / 32;
    k_prep<<<nvblocks, 256>>>(input, (__half*)pxTh, (__half*)pmrh, (__half*)pmd,
                              (float*)pcr, (float*)pcd, n);

    const int nchunks = (e + 31) / 32;      // one warp per 32-edge chunk
    const int eblocks = (nchunks + 7) / 8;  // 8 warps per block
    k_edge_pass<<<eblocks, 256>>>(ei, ej, wr, wd,
                                  (const __half*)pxTh,
                                  (__half*)pmrh, (__half*)pmd,
                                  (float*)pcr, (float*)pcd, e);

    k_combine<<<nvblocks, 256>>>(input,
                                 (const __half*)pmrh, (const __half*)pmd,
                                 (const float*)pcr, (const float*)pcd,
                                 br, bd, out, n);
}